// round 11
// baseline (speedup 1.0000x reference)
#include <cuda_runtime.h>
#include <cuda_fp16.h>
#include <cstdint>

#define DIM 512
#define HEADS 8
#define DHEAD 64
#define BATCH 4
#define NSEQ 2048
#define ROWS (BATCH * NSEQ)   // 8192

// ================= scratch (no allocations allowed) =================
__device__ __half g_xnh[ROWS * DIM], g_xnl[ROWS * DIM];
__device__ __half g_qh[ROWS * DIM], g_ql[ROWS * DIM];
__device__ __half g_kh[ROWS * DIM], g_kl[ROWS * DIM];
__device__ __half g_vh[ROWS * DIM], g_vl[ROWS * DIM];
__device__ __half g_ath[ROWS * DIM], g_atl[ROWS * DIM];
__device__ __half g_wqh[DIM * DIM], g_wql[DIM * DIM];
__device__ __half g_wkh[DIM * DIM], g_wkl[DIM * DIM];
__device__ __half g_wvh[DIM * DIM], g_wvl[DIM * DIM];
__device__ __half g_woh[DIM * DIM], g_wol[DIM * DIM];

// ================= helpers =================
__device__ __forceinline__ uint32_t smem_u32(const void* p) {
    uint32_t a;
    asm("{ .reg .u64 t; cvta.to.shared.u64 t, %1; cvt.u32.u64 %0, t; }" : "=r"(a) : "l"(p));
    return a;
}
__device__ __forceinline__ void ldsm4(uint32_t* r, uint32_t a) {
    asm volatile("ldmatrix.sync.aligned.m8n8.x4.shared.b16 {%0,%1,%2,%3}, [%4];"
                 : "=r"(r[0]), "=r"(r[1]), "=r"(r[2]), "=r"(r[3]) : "r"(a));
}
__device__ __forceinline__ void ldsm4t(uint32_t* r, uint32_t a) {
    asm volatile("ldmatrix.sync.aligned.m8n8.x4.trans.shared.b16 {%0,%1,%2,%3}, [%4];"
                 : "=r"(r[0]), "=r"(r[1]), "=r"(r[2]), "=r"(r[3]) : "r"(a));
}
// f32-accumulator fp16 MMA (main term)
__device__ __forceinline__ void mmaf32(float* c, const uint32_t* a, const uint32_t* b) {
    asm volatile("mma.sync.aligned.m16n8k16.row.col.f32.f16.f16.f32 "
                 "{%0,%1,%2,%3}, {%4,%5,%6,%7}, {%8,%9}, {%0,%1,%2,%3};"
                 : "+f"(c[0]), "+f"(c[1]), "+f"(c[2]), "+f"(c[3])
                 : "r"(a[0]), "r"(a[1]), "r"(a[2]), "r"(a[3]), "r"(b[0]), "r"(b[1]));
}
// f16-accumulator fp16 MMA (correction terms; D/C are 2x f16x2 regs)
__device__ __forceinline__ void mmaf16(uint32_t* c, const uint32_t* a, const uint32_t* b) {
    asm volatile("mma.sync.aligned.m16n8k16.row.col.f16.f16.f16.f16 "
                 "{%0,%1}, {%2,%3,%4,%5}, {%6,%7}, {%0,%1};"
                 : "+r"(c[0]), "+r"(c[1])
                 : "r"(a[0]), "r"(a[1]), "r"(a[2]), "r"(a[3]), "r"(b[0]), "r"(b[1]));
}
__device__ __forceinline__ void cpa16(uint32_t d, const void* s) {
    asm volatile("cp.async.cg.shared.global [%0], [%1], 16;" :: "r"(d), "l"(s));
}
#define CP_COMMIT() asm volatile("cp.async.commit_group;")
#define CP_WAIT(n)  asm volatile("cp.async.wait_group %0;" :: "n"(n))

__device__ __forceinline__ uint32_t h2pack(float a, float b) {
    __half2 t = __floats2half2_rn(a, b);
    return *reinterpret_cast<uint32_t*>(&t);
}
__device__ __forceinline__ float hres(float a) {
    __half h = __float2half_rn(a);
    return a - __half2float(h);
}
__device__ __forceinline__ float2 hup(uint32_t v) {
    __half2 h = *reinterpret_cast<__half2*>(&v);
    return __half22float2(h);
}

// ================= LayerNorm -> fp16 hi/lo =================
__global__ __launch_bounds__(256) void ln_kernel(const float* __restrict__ x,
                                                 const float* __restrict__ w,
                                                 const float* __restrict__ b) {
    __shared__ float sb1[8], sb2[8];
    int row = blockIdx.x, t = threadIdx.x;
    const float* xr = x + (size_t)row * DIM;
    float v0 = xr[t], v1 = xr[t + 256];
    float s = v0 + v1, ss = v0 * v0 + v1 * v1;
    #pragma unroll
    for (int o = 16; o > 0; o >>= 1) {
        s  += __shfl_xor_sync(~0u, s, o);
        ss += __shfl_xor_sync(~0u, ss, o);
    }
    int lane = t & 31, wd = t >> 5;
    if (lane == 0) { sb1[wd] = s; sb2[wd] = ss; }
    __syncthreads();
    if (wd == 0) {
        float r1 = (lane < 8) ? sb1[lane] : 0.f, r2 = (lane < 8) ? sb2[lane] : 0.f;
        #pragma unroll
        for (int o = 4; o > 0; o >>= 1) {
            r1 += __shfl_xor_sync(~0u, r1, o);
            r2 += __shfl_xor_sync(~0u, r2, o);
        }
        if (lane == 0) { sb1[0] = r1; sb2[0] = r2; }
    }
    __syncthreads();
    float mu  = sb1[0] * (1.f / DIM);
    float var = sb2[0] * (1.f / DIM) - mu * mu;
    float inv = rsqrtf(var + 1e-5f);
    float o0 = (v0 - mu) * inv * w[t] + b[t];
    float o1 = (v1 - mu) * inv * w[t + 256] + b[t + 256];
    size_t base = (size_t)row * DIM;
    g_xnh[base + t] = __float2half_rn(o0);
    g_xnh[base + t + 256] = __float2half_rn(o1);
    g_xnl[base + t] = __float2half_rn(hres(o0));
    g_xnl[base + t + 256] = __float2half_rn(hres(o1));
}

// ================= weight-norm -> fp16 hi/lo =================
__global__ __launch_bounds__(256) void wnorm_kernel(const float* __restrict__ wv_v,
                                                    const float* __restrict__ wv_g) {
    __shared__ float sbuf[8];
    int row = blockIdx.x, t = threadIdx.x;
    const float* vr = wv_v + (size_t)row * DIM;
    float v0 = vr[t], v1 = vr[t + 256];
    float ss = v0 * v0 + v1 * v1;
    #pragma unroll
    for (int o = 16; o > 0; o >>= 1) ss += __shfl_xor_sync(~0u, ss, o);
    int lane = t & 31, wd = t >> 5;
    if (lane == 0) sbuf[wd] = ss;
    __syncthreads();
    if (wd == 0) {
        float r = (lane < 8) ? sbuf[lane] : 0.f;
        #pragma unroll
        for (int o = 4; o > 0; o >>= 1) r += __shfl_xor_sync(~0u, r, o);
        if (lane == 0) sbuf[0] = r;
    }
    __syncthreads();
    float sc = wv_g[row] * rsqrtf(sbuf[0]);
    float o0 = v0 * sc, o1 = v1 * sc;
    size_t base = (size_t)row * DIM;
    g_wvh[base + t] = __float2half_rn(o0);
    g_wvh[base + t + 256] = __float2half_rn(o1);
    g_wvl[base + t] = __float2half_rn(hres(o0));
    g_wvl[base + t + 256] = __float2half_rn(hres(o1));
}

// ================= fp32 -> fp16 hi/lo =================
__global__ __launch_bounds__(256) void conv_kernel(const float* __restrict__ src,
                                                   __half* __restrict__ hi,
                                                   __half* __restrict__ lo, int n) {
    int i = blockIdx.x * 256 + threadIdx.x;
    if (i < n) {
        float f = src[i];
        hi[i] = __float2half_rn(f);
        lo[i] = __float2half_rn(hres(f));
    }
}

// ================= GEMM: BK=64, double-buffered, occ 1 =================
#define GP 144
#define TT (128 * GP)        // 18432 per tile
#define ST (4 * TT)          // 73728 per stage
#define G_SMEM (2 * ST)      // 147456

template <bool F16OUT>
__global__ __launch_bounds__(256, 1)
void gemm_h3(const __half* __restrict__ Ah, const __half* __restrict__ Al,
             const __half* __restrict__ Bh, const __half* __restrict__ Bl,
             float* __restrict__ Cf, __half* __restrict__ Ch,
             __half* __restrict__ Cl, float scale) {
    extern __shared__ char sm[];
    uint32_t sb = smem_u32(sm);
    int tid = threadIdx.x, lane = tid & 31, wd = tid >> 5;
    int wm = wd & 3, wn = wd >> 2;
    int tm = blockIdx.y * 128, tn = blockIdx.x * 128;

    float c[2][8][4];
    uint32_t cc[2][8][2];
    #pragma unroll
    for (int i = 0; i < 2; i++)
        #pragma unroll
        for (int j = 0; j < 8; j++) {
            #pragma unroll
            for (int e = 0; e < 4; e++) c[i][j][e] = 0.f;
            cc[i][j][0] = 0u; cc[i][j][1] = 0u;
        }

    auto stage = [&](int kc, uint32_t buf) {
        int k0 = kc * 64;
        #pragma unroll
        for (int u = 0; u < 4; u++) {
            int e = tid + u * 256;
            int r = e >> 3, c8 = (e & 7) * 8;
            uint32_t d = buf + (uint32_t)r * GP + c8 * 2;
            size_t ga = (size_t)(tm + r) * DIM + k0 + c8;
            size_t gb = (size_t)(tn + r) * DIM + k0 + c8;
            cpa16(d, &Ah[ga]);           cpa16(d + TT, &Al[ga]);
            cpa16(d + 2 * TT, &Bh[gb]);  cpa16(d + 3 * TT, &Bl[gb]);
        }
    };

    stage(0, sb);
    CP_COMMIT();

    for (int kc = 0; kc < 8; kc++) {
        CP_WAIT(0);
        __syncthreads();
        if (kc < 7) {
            stage(kc + 1, sb + ((kc + 1) & 1) * ST);
            CP_COMMIT();
        }
        uint32_t buf = sb + (kc & 1) * ST;
        #pragma unroll
        for (int ks = 0; ks < 4; ks++) {
            uint32_t ah[2][4], al[2][4];
            uint32_t acol = ks * 32 + ((lane >> 4) << 4);
            #pragma unroll
            for (int mt = 0; mt < 2; mt++) {
                uint32_t arow = wm * 32 + mt * 16 + (lane & 15);
                ldsm4(ah[mt], buf + arow * GP + acol);
                ldsm4(al[mt], buf + TT + arow * GP + acol);
            }
            uint32_t bro = ((lane >> 4) << 3) + (lane & 7);
            uint32_t bcol = ks * 32 + (((lane >> 3) & 1) << 4);
            #pragma unroll
            for (int p = 0; p < 4; p++) {
                uint32_t nrow = wn * 64 + p * 16 + bro;
                uint32_t bh[4], bl[4];
                ldsm4(bh, buf + 2 * TT + nrow * GP + bcol);
                ldsm4(bl, buf + 3 * TT + nrow * GP + bcol);
                #pragma unroll
                for (int mt = 0; mt < 2; mt++) {
                    mmaf32(c[mt][2 * p],      ah[mt], &bh[0]);
                    mmaf16(cc[mt][2 * p],     ah[mt], &bl[0]);
                    mmaf16(cc[mt][2 * p],     al[mt], &bh[0]);
                    mmaf32(c[mt][2 * p + 1],  ah[mt], &bh[2]);
                    mmaf16(cc[mt][2 * p + 1], ah[mt], &bl[2]);
                    mmaf16(cc[mt][2 * p + 1], al[mt], &bh[2]);
                }
            }
        }
        __syncthreads();
    }

    int g = lane >> 2, t4 = lane & 3;
    #pragma unroll
    for (int mt = 0; mt < 2; mt++) {
        #pragma unroll
        for (int nt = 0; nt < 8; nt++) {
            int row = tm + wm * 32 + mt * 16 + g;
            int col = tn + wn * 64 + nt * 8 + t4 * 2;
            float2 e0 = hup(cc[mt][nt][0]);
            float2 e1 = hup(cc[mt][nt][1]);
            float x0 = (c[mt][nt][0] + e0.x) * scale, x1 = (c[mt][nt][1] + e0.y) * scale;
            float y0 = (c[mt][nt][2] + e1.x) * scale, y1 = (c[mt][nt][3] + e1.y) * scale;
            if (F16OUT) {
                *(uint32_t*)&Ch[(size_t)row * DIM + col]       = h2pack(x0, x1);
                *(uint32_t*)&Cl[(size_t)row * DIM + col]       = h2pack(hres(x0), hres(x1));
                *(uint32_t*)&Ch[(size_t)(row + 8) * DIM + col] = h2pack(y0, y1);
                *(uint32_t*)&Cl[(size_t)(row + 8) * DIM + col] = h2pack(hres(y0), hres(y1));
            } else {
                *(float2*)&Cf[(size_t)row * DIM + col]       = make_float2(x0, x1);
                *(float2*)&Cf[(size_t)(row + 8) * DIM + col] = make_float2(y0, y1);
            }
        }
    }
}

// ================= flash attention: 64-row j-tiles, 2-stage, occ 1 =================
#define AST (64 * GP)           // 9216 per tile
#define A_SMEM (2 * 4 * AST)    // 73728
#define QL_OFF (128 * GP)

__global__ __launch_bounds__(256, 1)
void attn_mma(const __half* __restrict__ Qh, const __half* __restrict__ Ql,
              const __half* __restrict__ Kh, const __half* __restrict__ Kl,
              const __half* __restrict__ Vh, const __half* __restrict__ Vl,
              __half* __restrict__ Oh, __half* __restrict__ Ol) {
    extern __shared__ char sm[];
    uint32_t sb = smem_u32(sm);
    int tid = threadIdx.x, lane = tid & 31, wd = tid >> 5;
    int b = blockIdx.x >> 3, h = blockIdx.x & 7;
    int iBase = blockIdx.y * 128;
    size_t base = (size_t)b * NSEQ * DIM + (size_t)h * DHEAD;

    // ---- stage Q (pre-scaled by 1/8 in projection) ----
    #pragma unroll
    for (int u = 0; u < 4; u++) {
        int e = tid + u * 256;
        int r = e >> 3, c8 = (e & 7) * 8;
        uint32_t d = sb + (uint32_t)r * GP + c8 * 2;
        size_t ga = base + (size_t)(iBase + r) * DIM + c8;
        cpa16(d, &Qh[ga]);
        cpa16(d + QL_OFF, &Ql[ga]);
    }
    CP_COMMIT(); CP_WAIT(0);
    __syncthreads();

    uint32_t qh[4][4], ql[4][4];
    {
        uint32_t arow = wd * 16 + (lane & 15);
        #pragma unroll
        for (int ks = 0; ks < 4; ks++) {
            uint32_t acol = ks * 32 + ((lane >> 4) << 4);
            ldsm4(qh[ks], sb + arow * GP + acol);
            ldsm4(ql[ks], sb + QL_OFF + arow * GP + acol);
        }
    }
    __syncthreads();

    float o[8][4];
    uint32_t oc[8][2];
    #pragma unroll
    for (int i = 0; i < 8; i++) {
        #pragma unroll
        for (int e = 0; e < 4; e++) o[i][e] = 0.f;
        oc[i][0] = 0u; oc[i][1] = 0u;
    }
    float l0 = 0.f, l1 = 0.f;

    auto stage_kv = [&](int blk, uint32_t buf) {
        int j0 = blk * 64;
        #pragma unroll
        for (int u = 0; u < 2; u++) {
            int e = tid + u * 256;
            int r = e >> 3, c8 = (e & 7) * 8;
            uint32_t d = buf + (uint32_t)r * GP + c8 * 2;
            size_t ga = base + (size_t)(j0 + r) * DIM + c8;
            cpa16(d + 0 * AST, &Kh[ga]);
            cpa16(d + 1 * AST, &Kl[ga]);
            cpa16(d + 2 * AST, &Vh[ga]);
            cpa16(d + 3 * AST, &Vl[ga]);
        }
    };

    stage_kv(0, sb);
    CP_COMMIT();

    for (int bi = 0; bi < 32; bi++) {
        CP_WAIT(0);
        __syncthreads();
        uint32_t buf = sb + (bi & 1) * 4 * AST;
        if (bi < 31) {
            stage_kv(bi + 1, sb + ((bi + 1) & 1) * 4 * AST);
            CP_COMMIT();
        }

        // ---- S = (Q/8) K^T ----
        float s[8][4];
        uint32_t scn[8][2];
        #pragma unroll
        for (int nt = 0; nt < 8; nt++) {
            #pragma unroll
            for (int e = 0; e < 4; e++) s[nt][e] = 0.f;
            scn[nt][0] = 0u; scn[nt][1] = 0u;
        }

        uint32_t bro = ((lane >> 4) << 3) + (lane & 7);
        #pragma unroll
        for (int ks = 0; ks < 4; ks++) {
            uint32_t bcol = ks * 32 + (((lane >> 3) & 1) << 4);
            #pragma unroll
            for (int p = 0; p < 4; p++) {
                uint32_t nrow = p * 16 + bro;
                uint32_t bh[4], bl[4];
                ldsm4(bh, buf + 0 * AST + nrow * GP + bcol);
                ldsm4(bl, buf + 1 * AST + nrow * GP + bcol);
                mmaf32(s[2 * p],       qh[ks], &bh[0]);
                mmaf16(scn[2 * p],     qh[ks], &bl[0]);
                mmaf16(scn[2 * p],     ql[ks], &bh[0]);
                mmaf32(s[2 * p + 1],   qh[ks], &bh[2]);
                mmaf16(scn[2 * p + 1], qh[ks], &bl[2]);
                mmaf16(scn[2 * p + 1], ql[ks], &bh[2]);
            }
        }

        // ---- exp (no max-subtraction; scores are provably small) ----
        #pragma unroll
        for (int nt = 0; nt < 8; nt++) {
            float2 e0 = hup(scn[nt][0]);
            float2 e1 = hup(scn[nt][1]);
            s[nt][0] = __expf(s[nt][0] + e0.x);
            s[nt][1] = __expf(s[nt][1] + e0.y);
            s[nt][2] = __expf(s[nt][2] + e1.x);
            s[nt][3] = __expf(s[nt][3] + e1.y);
            l0 += s[nt][0] + s[nt][1];
            l1 += s[nt][2] + s[nt][3];
        }

        // ---- O += P V ----
        uint32_t vro = (((lane >> 3) & 1) << 3) + (lane & 7);
        uint32_t vco = (lane >> 4) << 4;
        #pragma unroll
        for (int st = 0; st < 4; st++) {
            uint32_t a_h[4], a_l[4];
            a_h[0] = h2pack(s[2 * st][0], s[2 * st][1]);
            a_h[1] = h2pack(s[2 * st][2], s[2 * st][3]);
            a_h[2] = h2pack(s[2 * st + 1][0], s[2 * st + 1][1]);
            a_h[3] = h2pack(s[2 * st + 1][2], s[2 * st + 1][3]);
            a_l[0] = h2pack(hres(s[2 * st][0]), hres(s[2 * st][1]));
            a_l[1] = h2pack(hres(s[2 * st][2]), hres(s[2 * st][3]));
            a_l[2] = h2pack(hres(s[2 * st + 1][0]), hres(s[2 * st + 1][1]));
            a_l[3] = h2pack(hres(s[2 * st + 1][2]), hres(s[2 * st + 1][3]));
            uint32_t jrow = st * 16 + vro;
            #pragma unroll
            for (int dp = 0; dp < 4; dp++) {
                uint32_t db = dp * 32 + vco;
                uint32_t vh[4], vl[4];
                ldsm4t(vh, buf + 2 * AST + jrow * GP + db);
                ldsm4t(vl, buf + 3 * AST + jrow * GP + db);
                mmaf32(o[2 * dp],      a_h, &vh[0]);
                mmaf16(oc[2 * dp],     a_h, &vl[0]);
                mmaf16(oc[2 * dp],     a_l, &vh[0]);
                mmaf32(o[2 * dp + 1],  a_h, &vh[2]);
                mmaf16(oc[2 * dp + 1], a_h, &vl[2]);
                mmaf16(oc[2 * dp + 1], a_l, &vh[2]);
            }
        }
        __syncthreads();
    }

    l0 += __shfl_xor_sync(~0u, l0, 1); l0 += __shfl_xor_sync(~0u, l0, 2);
    l1 += __shfl_xor_sync(~0u, l1, 1); l1 += __shfl_xor_sync(~0u, l1, 2);
    float i0v = 1.f / l0, i1v = 1.f / l1;

    int g = lane >> 2, t4 = lane & 3;
    size_t ga0 = base + (size_t)(iBase + wd * 16 + g) * DIM + t4 * 2;
    size_t ga1 = ga0 + 8 * DIM;
    #pragma unroll
    for (int dt = 0; dt < 8; dt++) {
        float2 e0 = hup(oc[dt][0]);
        float2 e1 = hup(oc[dt][1]);
        float x0 = (o[dt][0] + e0.x) * i0v, x1 = (o[dt][1] + e0.y) * i0v;
        float y0 = (o[dt][2] + e1.x) * i1v, y1 = (o[dt][3] + e1.y) * i1v;
        *(uint32_t*)&Oh[ga0 + dt * 8] = h2pack(x0, x1);
        *(uint32_t*)&Ol[ga0 + dt * 8] = h2pack(hres(x0), hres(x1));
        *(uint32_t*)&Oh[ga1 + dt * 8] = h2pack(y0, y1);
        *(uint32_t*)&Ol[ga1 + dt * 8] = h2pack(hres(y0), hres(y1));
    }
}

// ================= launch =================
extern "C" void kernel_launch(void* const* d_in, const int* in_sizes, int n_in,
                              void* d_out, int out_size) {
    const float* x     = (const float*)d_in[0];
    const float* ln_w  = (const float*)d_in[1];
    const float* ln_b  = (const float*)d_in[2];
    const float* wq    = (const float*)d_in[3];
    const float* wk    = (const float*)d_in[4];
    const float* wv_v  = (const float*)d_in[5];
    const float* wv_g  = (const float*)d_in[6];
    const float* w_out = (const float*)d_in[7];
    float* out = (float*)d_out;

    __half *xnh, *xnl, *ath, *atl;
    __half *qh, *ql, *kh, *kl, *vh, *vl;
    __half *wqh, *wql, *wkh, *wkl, *wvh, *wvl, *woh, *wol;
    cudaGetSymbolAddress((void**)&xnh, g_xnh); cudaGetSymbolAddress((void**)&xnl, g_xnl);
    cudaGetSymbolAddress((void**)&ath, g_ath); cudaGetSymbolAddress((void**)&atl, g_atl);
    cudaGetSymbolAddress((void**)&qh, g_qh); cudaGetSymbolAddress((void**)&ql, g_ql);
    cudaGetSymbolAddress((void**)&kh, g_kh); cudaGetSymbolAddress((void**)&kl, g_kl);
    cudaGetSymbolAddress((void**)&vh, g_vh); cudaGetSymbolAddress((void**)&vl, g_vl);
    cudaGetSymbolAddress((void**)&wqh, g_wqh); cudaGetSymbolAddress((void**)&wql, g_wql);
    cudaGetSymbolAddress((void**)&wkh, g_wkh); cudaGetSymbolAddress((void**)&wkl, g_wkl);
    cudaGetSymbolAddress((void**)&wvh, g_wvh); cudaGetSymbolAddress((void**)&wvl, g_wvl);
    cudaGetSymbolAddress((void**)&woh, g_woh); cudaGetSymbolAddress((void**)&wol, g_wol);

    cudaFuncSetAttribute(gemm_h3<true>,  cudaFuncAttributeMaxDynamicSharedMemorySize, G_SMEM);
    cudaFuncSetAttribute(gemm_h3<false>, cudaFuncAttributeMaxDynamicSharedMemorySize, G_SMEM);
    cudaFuncSetAttribute(attn_mma, cudaFuncAttributeMaxDynamicSharedMemorySize, A_SMEM);

    dim3 gg(DIM / 128, ROWS / 128);  // (4, 64)

    conv_kernel<<<(DIM * DIM + 255) / 256, 256>>>(wq, wqh, wql, DIM * DIM);
    ln_kernel<<<ROWS, 256>>>(x, ln_w, ln_b);
    gemm_h3<true><<<gg, 256, G_SMEM>>>(xnh, xnl, wqh, wql, nullptr, qh, ql, 0.125f);

    conv_kernel<<<(DIM * DIM + 255) / 256, 256>>>(wk, wkh, wkl, DIM * DIM);
    gemm_h3<true><<<gg, 256, G_SMEM>>>(xnh, xnl, wkh, wkl, nullptr, kh, kl, 1.0f);

    wnorm_kernel<<<DIM, 256>>>(wv_v, wv_g);
    gemm_h3<true><<<gg, 256, G_SMEM>>>(xnh, xnl, wvh, wvl, nullptr, vh, vl, 1.0f);

    conv_kernel<<<(DIM * DIM + 255) / 256, 256>>>(w_out, woh, wol, DIM * DIM);

    attn_mma<<<dim3(32, 16), 256, A_SMEM>>>(qh, ql, kh, kl, vh, vl, ath, atl);

    gemm_h3<false><<<gg, 256, G_SMEM>>>(ath, atl, woh, wol, out, nullptr, nullptr, 1.0f);
}

// round 12
// speedup vs baseline: 1.0890x; 1.0890x over previous
#include <cuda_runtime.h>
#include <cuda_fp16.h>
#include <cstdint>

#define DIM 512
#define HEADS 8
#define DHEAD 64
#define BATCH 4
#define NSEQ 2048
#define ROWS (BATCH * NSEQ)   // 8192

// ================= scratch (no allocations allowed) =================
__device__ __half g_xnh[ROWS * DIM], g_xnl[ROWS * DIM];
__device__ __half g_qh[ROWS * DIM];
__device__ __half g_kh[ROWS * DIM];
__device__ __half g_vh[ROWS * DIM];
__device__ __half g_ath[ROWS * DIM], g_atl[ROWS * DIM];
__device__ __half g_wqh[DIM * DIM], g_wql[DIM * DIM];
__device__ __half g_wkh[DIM * DIM], g_wkl[DIM * DIM];
__device__ __half g_wvh[DIM * DIM], g_wvl[DIM * DIM];
__device__ __half g_woh[DIM * DIM], g_wol[DIM * DIM];

// ================= helpers =================
__device__ __forceinline__ uint32_t smem_u32(const void* p) {
    uint32_t a;
    asm("{ .reg .u64 t; cvta.to.shared.u64 t, %1; cvt.u32.u64 %0, t; }" : "=r"(a) : "l"(p));
    return a;
}
__device__ __forceinline__ void ldsm4(uint32_t* r, uint32_t a) {
    asm volatile("ldmatrix.sync.aligned.m8n8.x4.shared.b16 {%0,%1,%2,%3}, [%4];"
                 : "=r"(r[0]), "=r"(r[1]), "=r"(r[2]), "=r"(r[3]) : "r"(a));
}
__device__ __forceinline__ void ldsm4t(uint32_t* r, uint32_t a) {
    asm volatile("ldmatrix.sync.aligned.m8n8.x4.trans.shared.b16 {%0,%1,%2,%3}, [%4];"
                 : "=r"(r[0]), "=r"(r[1]), "=r"(r[2]), "=r"(r[3]) : "r"(a));
}
__device__ __forceinline__ void mmaf32(float* c, const uint32_t* a, const uint32_t* b) {
    asm volatile("mma.sync.aligned.m16n8k16.row.col.f32.f16.f16.f32 "
                 "{%0,%1,%2,%3}, {%4,%5,%6,%7}, {%8,%9}, {%0,%1,%2,%3};"
                 : "+f"(c[0]), "+f"(c[1]), "+f"(c[2]), "+f"(c[3])
                 : "r"(a[0]), "r"(a[1]), "r"(a[2]), "r"(a[3]), "r"(b[0]), "r"(b[1]));
}
__device__ __forceinline__ void cpa16(uint32_t d, const void* s) {
    asm volatile("cp.async.cg.shared.global [%0], [%1], 16;" :: "r"(d), "l"(s));
}
#define CP_COMMIT() asm volatile("cp.async.commit_group;")
#define CP_WAIT(n)  asm volatile("cp.async.wait_group %0;" :: "n"(n))

__device__ __forceinline__ uint32_t h2pack(float a, float b) {
    __half2 t = __floats2half2_rn(a, b);
    return *reinterpret_cast<uint32_t*>(&t);
}
__device__ __forceinline__ float hres(float a) {
    __half h = __float2half_rn(a);
    return a - __half2float(h);
}

// ================= LayerNorm -> fp16 hi/lo =================
__global__ __launch_bounds__(256) void ln_kernel(const float* __restrict__ x,
                                                 const float* __restrict__ w,
                                                 const float* __restrict__ b) {
    __shared__ float sb1[8], sb2[8];
    int row = blockIdx.x, t = threadIdx.x;
    const float* xr = x + (size_t)row * DIM;
    float v0 = xr[t], v1 = xr[t + 256];
    float s = v0 + v1, ss = v0 * v0 + v1 * v1;
    #pragma unroll
    for (int o = 16; o > 0; o >>= 1) {
        s  += __shfl_xor_sync(~0u, s, o);
        ss += __shfl_xor_sync(~0u, ss, o);
    }
    int lane = t & 31, wd = t >> 5;
    if (lane == 0) { sb1[wd] = s; sb2[wd] = ss; }
    __syncthreads();
    if (wd == 0) {
        float r1 = (lane < 8) ? sb1[lane] : 0.f, r2 = (lane < 8) ? sb2[lane] : 0.f;
        #pragma unroll
        for (int o = 4; o > 0; o >>= 1) {
            r1 += __shfl_xor_sync(~0u, r1, o);
            r2 += __shfl_xor_sync(~0u, r2, o);
        }
        if (lane == 0) { sb1[0] = r1; sb2[0] = r2; }
    }
    __syncthreads();
    float mu  = sb1[0] * (1.f / DIM);
    float var = sb2[0] * (1.f / DIM) - mu * mu;
    float inv = rsqrtf(var + 1e-5f);
    float o0 = (v0 - mu) * inv * w[t] + b[t];
    float o1 = (v1 - mu) * inv * w[t + 256] + b[t + 256];
    size_t base = (size_t)row * DIM;
    g_xnh[base + t] = __float2half_rn(o0);
    g_xnh[base + t + 256] = __float2half_rn(o1);
    g_xnl[base + t] = __float2half_rn(hres(o0));
    g_xnl[base + t + 256] = __float2half_rn(hres(o1));
}

// ================= weight-norm -> fp16 hi/lo =================
__global__ __launch_bounds__(256) void wnorm_kernel(const float* __restrict__ wv_v,
                                                    const float* __restrict__ wv_g) {
    __shared__ float sbuf[8];
    int row = blockIdx.x, t = threadIdx.x;
    const float* vr = wv_v + (size_t)row * DIM;
    float v0 = vr[t], v1 = vr[t + 256];
    float ss = v0 * v0 + v1 * v1;
    #pragma unroll
    for (int o = 16; o > 0; o >>= 1) ss += __shfl_xor_sync(~0u, ss, o);
    int lane = t & 31, wd = t >> 5;
    if (lane == 0) sbuf[wd] = ss;
    __syncthreads();
    if (wd == 0) {
        float r = (lane < 8) ? sbuf[lane] : 0.f;
        #pragma unroll
        for (int o = 4; o > 0; o >>= 1) r += __shfl_xor_sync(~0u, r, o);
        if (lane == 0) sbuf[0] = r;
    }
    __syncthreads();
    float sc = wv_g[row] * rsqrtf(sbuf[0]);
    float o0 = v0 * sc, o1 = v1 * sc;
    size_t base = (size_t)row * DIM;
    g_wvh[base + t] = __float2half_rn(o0);
    g_wvh[base + t + 256] = __float2half_rn(o1);
    g_wvl[base + t] = __float2half_rn(hres(o0));
    g_wvl[base + t + 256] = __float2half_rn(hres(o1));
}

// ================= fp32 -> fp16 hi/lo =================
__global__ __launch_bounds__(256) void conv_kernel(const float* __restrict__ src,
                                                   __half* __restrict__ hi,
                                                   __half* __restrict__ lo, int n) {
    int i = blockIdx.x * 256 + threadIdx.x;
    if (i < n) {
        float f = src[i];
        hi[i] = __float2half_rn(f);
        lo[i] = __float2half_rn(hres(f));
    }
}

// ================= GEMM: 3-term fp16, BK=64, double-buffered =================
// MODE 0: fp32 out. MODE 1: fp16 hi/lo out. MODE 2: fp16 hi only out.
#define GP 144
#define TT (128 * GP)        // 18432 per tile
#define ST (4 * TT)          // 73728 per stage
#define G_SMEM (2 * ST)      // 147456

template <int MODE>
__global__ __launch_bounds__(256, 1)
void gemm_h3(const __half* __restrict__ Ah, const __half* __restrict__ Al,
             const __half* __restrict__ Bh, const __half* __restrict__ Bl,
             float* __restrict__ Cf, __half* __restrict__ Ch,
             __half* __restrict__ Cl, float scale) {
    extern __shared__ char sm[];
    uint32_t sb = smem_u32(sm);
    int tid = threadIdx.x, lane = tid & 31, wd = tid >> 5;
    int wm = wd & 3, wn = wd >> 2;
    int tm = blockIdx.y * 128, tn = blockIdx.x * 128;

    float c[2][8][4];
    #pragma unroll
    for (int i = 0; i < 2; i++)
        #pragma unroll
        for (int j = 0; j < 8; j++)
            #pragma unroll
            for (int e = 0; e < 4; e++) c[i][j][e] = 0.f;

    auto stage = [&](int kc, uint32_t buf) {
        int k0 = kc * 64;
        #pragma unroll
        for (int u = 0; u < 4; u++) {
            int e = tid + u * 256;
            int r = e >> 3, c8 = (e & 7) * 8;
            uint32_t d = buf + (uint32_t)r * GP + c8 * 2;
            size_t ga = (size_t)(tm + r) * DIM + k0 + c8;
            size_t gb = (size_t)(tn + r) * DIM + k0 + c8;
            cpa16(d, &Ah[ga]);           cpa16(d + TT, &Al[ga]);
            cpa16(d + 2 * TT, &Bh[gb]);  cpa16(d + 3 * TT, &Bl[gb]);
        }
    };

    stage(0, sb);
    CP_COMMIT();

    for (int kc = 0; kc < 8; kc++) {
        CP_WAIT(0);
        __syncthreads();
        if (kc < 7) {
            stage(kc + 1, sb + ((kc + 1) & 1) * ST);
            CP_COMMIT();
        }
        uint32_t buf = sb + (kc & 1) * ST;
        #pragma unroll
        for (int ks = 0; ks < 4; ks++) {
            uint32_t ah[2][4], al[2][4];
            uint32_t acol = ks * 32 + ((lane >> 4) << 4);
            #pragma unroll
            for (int mt = 0; mt < 2; mt++) {
                uint32_t arow = wm * 32 + mt * 16 + (lane & 15);
                ldsm4(ah[mt], buf + arow * GP + acol);
                ldsm4(al[mt], buf + TT + arow * GP + acol);
            }
            uint32_t bro = ((lane >> 4) << 3) + (lane & 7);
            uint32_t bcol = ks * 32 + (((lane >> 3) & 1) << 4);
            #pragma unroll
            for (int p = 0; p < 4; p++) {
                uint32_t nrow = wn * 64 + p * 16 + bro;
                uint32_t bh[4], bl[4];
                ldsm4(bh, buf + 2 * TT + nrow * GP + bcol);
                ldsm4(bl, buf + 3 * TT + nrow * GP + bcol);
                #pragma unroll
                for (int mt = 0; mt < 2; mt++) {
                    mmaf32(c[mt][2 * p],     ah[mt], &bh[0]);
                    mmaf32(c[mt][2 * p],     ah[mt], &bl[0]);
                    mmaf32(c[mt][2 * p],     al[mt], &bh[0]);
                    mmaf32(c[mt][2 * p + 1], ah[mt], &bh[2]);
                    mmaf32(c[mt][2 * p + 1], ah[mt], &bl[2]);
                    mmaf32(c[mt][2 * p + 1], al[mt], &bh[2]);
                }
            }
        }
        __syncthreads();
    }

    int g = lane >> 2, t4 = lane & 3;
    #pragma unroll
    for (int mt = 0; mt < 2; mt++) {
        #pragma unroll
        for (int nt = 0; nt < 8; nt++) {
            int row = tm + wm * 32 + mt * 16 + g;
            int col = tn + wn * 64 + nt * 8 + t4 * 2;
            float x0 = c[mt][nt][0] * scale, x1 = c[mt][nt][1] * scale;
            float y0 = c[mt][nt][2] * scale, y1 = c[mt][nt][3] * scale;
            if (MODE == 1) {
                *(uint32_t*)&Ch[(size_t)row * DIM + col]       = h2pack(x0, x1);
                *(uint32_t*)&Cl[(size_t)row * DIM + col]       = h2pack(hres(x0), hres(x1));
                *(uint32_t*)&Ch[(size_t)(row + 8) * DIM + col] = h2pack(y0, y1);
                *(uint32_t*)&Cl[(size_t)(row + 8) * DIM + col] = h2pack(hres(y0), hres(y1));
            } else if (MODE == 2) {
                *(uint32_t*)&Ch[(size_t)row * DIM + col]       = h2pack(x0, x1);
                *(uint32_t*)&Ch[(size_t)(row + 8) * DIM + col] = h2pack(y0, y1);
            } else {
                *(float2*)&Cf[(size_t)row * DIM + col]       = make_float2(x0, x1);
                *(float2*)&Cf[(size_t)(row + 8) * DIM + col] = make_float2(y0, y1);
            }
        }
    }
}

// ================= flash attention: 1-term fp16, 64-row j-tiles, occ 2 =================
// smem: 2 stages x (Kh, Vh), each 64 x GP bytes. Q hi staged once at offset 0.
#define AST (64 * GP)           // 9216 per tile
#define A_SMEM (2 * 2 * AST)    // 36864

__global__ __launch_bounds__(256, 2)
void attn_mma(const __half* __restrict__ Qh,
              const __half* __restrict__ Kh,
              const __half* __restrict__ Vh,
              __half* __restrict__ Oh, __half* __restrict__ Ol) {
    extern __shared__ char sm[];
    uint32_t sb = smem_u32(sm);
    int tid = threadIdx.x, lane = tid & 31, wd = tid >> 5;
    int b = blockIdx.x >> 3, h = blockIdx.x & 7;
    int iBase = blockIdx.y * 128;
    size_t base = (size_t)b * NSEQ * DIM + (size_t)h * DHEAD;

    // ---- stage Q hi (pre-scaled by 1/8 in projection) ----
    #pragma unroll
    for (int u = 0; u < 4; u++) {
        int e = tid + u * 256;
        int r = e >> 3, c8 = (e & 7) * 8;
        uint32_t d = sb + (uint32_t)r * GP + c8 * 2;
        size_t ga = base + (size_t)(iBase + r) * DIM + c8;
        cpa16(d, &Qh[ga]);
    }
    CP_COMMIT(); CP_WAIT(0);
    __syncthreads();

    uint32_t qh[4][4];
    {
        uint32_t arow = wd * 16 + (lane & 15);
        #pragma unroll
        for (int ks = 0; ks < 4; ks++) {
            uint32_t acol = ks * 32 + ((lane >> 4) << 4);
            ldsm4(qh[ks], sb + arow * GP + acol);
        }
    }
    __syncthreads();   // Q area reused by K/V stages

    float o[8][4];
    #pragma unroll
    for (int i = 0; i < 8; i++)
        #pragma unroll
        for (int e = 0; e < 4; e++) o[i][e] = 0.f;
    float l0 = 0.f, l1 = 0.f;

    auto stage_kv = [&](int blk, uint32_t buf) {
        int j0 = blk * 64;
        #pragma unroll
        for (int u = 0; u < 2; u++) {
            int e = tid + u * 256;
            int r = e >> 3, c8 = (e & 7) * 8;
            uint32_t d = buf + (uint32_t)r * GP + c8 * 2;
            size_t ga = base + (size_t)(j0 + r) * DIM + c8;
            cpa16(d, &Kh[ga]);
            cpa16(d + AST, &Vh[ga]);
        }
    };

    stage_kv(0, sb);
    CP_COMMIT();

    for (int bi = 0; bi < 32; bi++) {
        CP_WAIT(0);
        __syncthreads();
        uint32_t buf = sb + (bi & 1) * 2 * AST;
        if (bi < 31) {
            stage_kv(bi + 1, sb + ((bi + 1) & 1) * 2 * AST);
            CP_COMMIT();
        }

        // ---- S = (Q/8) K^T : 1 MMA per n8 tile ----
        float s[8][4];
        #pragma unroll
        for (int nt = 0; nt < 8; nt++)
            #pragma unroll
            for (int e = 0; e < 4; e++) s[nt][e] = 0.f;

        uint32_t bro = ((lane >> 4) << 3) + (lane & 7);
        #pragma unroll
        for (int ks = 0; ks < 4; ks++) {
            uint32_t bcol = ks * 32 + (((lane >> 3) & 1) << 4);
            #pragma unroll
            for (int p = 0; p < 4; p++) {
                uint32_t nrow = p * 16 + bro;
                uint32_t bh[4];
                ldsm4(bh, buf + nrow * GP + bcol);
                mmaf32(s[2 * p],     qh[ks], &bh[0]);
                mmaf32(s[2 * p + 1], qh[ks], &bh[2]);
            }
        }

        // ---- exp (no max-subtraction; scores are provably small) ----
        #pragma unroll
        for (int nt = 0; nt < 8; nt++) {
            s[nt][0] = __expf(s[nt][0]);
            s[nt][1] = __expf(s[nt][1]);
            s[nt][2] = __expf(s[nt][2]);
            s[nt][3] = __expf(s[nt][3]);
            l0 += s[nt][0] + s[nt][1];
            l1 += s[nt][2] + s[nt][3];
        }

        // ---- O += P V : 1 MMA per d8 tile ----
        uint32_t vro = (((lane >> 3) & 1) << 3) + (lane & 7);
        uint32_t vco = (lane >> 4) << 4;
        #pragma unroll
        for (int st = 0; st < 4; st++) {
            uint32_t a_h[4];
            a_h[0] = h2pack(s[2 * st][0], s[2 * st][1]);
            a_h[1] = h2pack(s[2 * st][2], s[2 * st][3]);
            a_h[2] = h2pack(s[2 * st + 1][0], s[2 * st + 1][1]);
            a_h[3] = h2pack(s[2 * st + 1][2], s[2 * st + 1][3]);
            uint32_t jrow = st * 16 + vro;
            #pragma unroll
            for (int dp = 0; dp < 4; dp++) {
                uint32_t db = dp * 32 + vco;
                uint32_t vh[4];
                ldsm4t(vh, buf + AST + jrow * GP + db);
                mmaf32(o[2 * dp],     a_h, &vh[0]);
                mmaf32(o[2 * dp + 1], a_h, &vh[2]);
            }
        }
        __syncthreads();
    }

    l0 += __shfl_xor_sync(~0u, l0, 1); l0 += __shfl_xor_sync(~0u, l0, 2);
    l1 += __shfl_xor_sync(~0u, l1, 1); l1 += __shfl_xor_sync(~0u, l1, 2);
    // store att * 16 so the lo residual stays in fp16 normal range
    float i0v = 16.f / l0, i1v = 16.f / l1;

    int g = lane >> 2, t4 = lane & 3;
    size_t ga0 = base + (size_t)(iBase + wd * 16 + g) * DIM + t4 * 2;
    size_t ga1 = ga0 + 8 * DIM;
    #pragma unroll
    for (int dt = 0; dt < 8; dt++) {
        float x0 = o[dt][0] * i0v, x1 = o[dt][1] * i0v;
        float y0 = o[dt][2] * i1v, y1 = o[dt][3] * i1v;
        *(uint32_t*)&Oh[ga0 + dt * 8] = h2pack(x0, x1);
        *(uint32_t*)&Ol[ga0 + dt * 8] = h2pack(hres(x0), hres(x1));
        *(uint32_t*)&Oh[ga1 + dt * 8] = h2pack(y0, y1);
        *(uint32_t*)&Ol[ga1 + dt * 8] = h2pack(hres(y0), hres(y1));
    }
}

// ================= launch =================
extern "C" void kernel_launch(void* const* d_in, const int* in_sizes, int n_in,
                              void* d_out, int out_size) {
    const float* x     = (const float*)d_in[0];
    const float* ln_w  = (const float*)d_in[1];
    const float* ln_b  = (const float*)d_in[2];
    const float* wq    = (const float*)d_in[3];
    const float* wk    = (const float*)d_in[4];
    const float* wv_v  = (const float*)d_in[5];
    const float* wv_g  = (const float*)d_in[6];
    const float* w_out = (const float*)d_in[7];
    float* out = (float*)d_out;

    __half *xnh, *xnl, *ath, *atl, *qh, *kh, *vh;
    __half *wqh, *wql, *wkh, *wkl, *wvh, *wvl, *woh, *wol;
    cudaGetSymbolAddress((void**)&xnh, g_xnh); cudaGetSymbolAddress((void**)&xnl, g_xnl);
    cudaGetSymbolAddress((void**)&ath, g_ath); cudaGetSymbolAddress((void**)&atl, g_atl);
    cudaGetSymbolAddress((void**)&qh, g_qh);
    cudaGetSymbolAddress((void**)&kh, g_kh);
    cudaGetSymbolAddress((void**)&vh, g_vh);
    cudaGetSymbolAddress((void**)&wqh, g_wqh); cudaGetSymbolAddress((void**)&wql, g_wql);
    cudaGetSymbolAddress((void**)&wkh, g_wkh); cudaGetSymbolAddress((void**)&wkl, g_wkl);
    cudaGetSymbolAddress((void**)&wvh, g_wvh); cudaGetSymbolAddress((void**)&wvl, g_wvl);
    cudaGetSymbolAddress((void**)&woh, g_woh); cudaGetSymbolAddress((void**)&wol, g_wol);

    cudaFuncSetAttribute(gemm_h3<0>, cudaFuncAttributeMaxDynamicSharedMemorySize, G_SMEM);
    cudaFuncSetAttribute(gemm_h3<1>, cudaFuncAttributeMaxDynamicSharedMemorySize, G_SMEM);
    cudaFuncSetAttribute(gemm_h3<2>, cudaFuncAttributeMaxDynamicSharedMemorySize, G_SMEM);
    cudaFuncSetAttribute(attn_mma, cudaFuncAttributeMaxDynamicSharedMemorySize, A_SMEM);

    dim3 gg(DIM / 128, ROWS / 128);  // (4, 64)

    conv_kernel<<<(DIM * DIM + 255) / 256, 256>>>(wq, wqh, wql, DIM * DIM);
    ln_kernel<<<ROWS, 256>>>(x, ln_w, ln_b);
    gemm_h3<2><<<gg, 256, G_SMEM>>>(xnh, xnl, wqh, wql, nullptr, qh, nullptr, 0.125f);

    conv_kernel<<<(DIM * DIM + 255) / 256, 256>>>(wk, wkh, wkl, DIM * DIM);
    gemm_h3<2><<<gg, 256, G_SMEM>>>(xnh, xnl, wkh, wkl, nullptr, kh, nullptr, 1.0f);

    wnorm_kernel<<<DIM, 256>>>(wv_v, wv_g);
    gemm_h3<2><<<gg, 256, G_SMEM>>>(xnh, xnl, wvh, wvl, nullptr, vh, nullptr, 1.0f);

    conv_kernel<<<(DIM * DIM + 255) / 256, 256>>>(w_out, woh, wol, DIM * DIM);

    attn_mma<<<dim3(32, 16), 256, A_SMEM>>>(qh, kh, vh, ath, atl);

    // att was stored x16; undo in the output projection
    gemm_h3<0><<<gg, 256, G_SMEM>>>(ath, atl, woh, wol, out, nullptr, nullptr, 1.0f / 16.0f);
}

// round 13
// speedup vs baseline: 1.9182x; 1.7614x over previous
#include <cuda_runtime.h>
#include <cuda_fp16.h>
#include <cstdint>

#define DIM 512
#define HEADS 8
#define DHEAD 64
#define BATCH 4
#define NSEQ 2048
#define ROWS (BATCH * NSEQ)   // 8192

// ================= scratch (no allocations allowed) =================
__device__ __half g_xnh[ROWS * DIM], g_xnl[ROWS * DIM];
__device__ __half g_qh[ROWS * DIM];
__device__ __half g_kh[ROWS * DIM];
__device__ __half g_vh[ROWS * DIM];
__device__ __half g_ath[ROWS * DIM], g_atl[ROWS * DIM];
__device__ __half g_wqh[DIM * DIM], g_wql[DIM * DIM];
__device__ __half g_wkh[DIM * DIM], g_wkl[DIM * DIM];
__device__ __half g_wvh[DIM * DIM], g_wvl[DIM * DIM];
__device__ __half g_woh[DIM * DIM], g_wol[DIM * DIM];

// ================= helpers =================
__device__ __forceinline__ uint32_t smem_u32(const void* p) {
    uint32_t a;
    asm("{ .reg .u64 t; cvta.to.shared.u64 t, %1; cvt.u32.u64 %0, t; }" : "=r"(a) : "l"(p));
    return a;
}
__device__ __forceinline__ void ldsm4(uint32_t* r, uint32_t a) {
    asm volatile("ldmatrix.sync.aligned.m8n8.x4.shared.b16 {%0,%1,%2,%3}, [%4];"
                 : "=r"(r[0]), "=r"(r[1]), "=r"(r[2]), "=r"(r[3]) : "r"(a));
}
__device__ __forceinline__ void ldsm4t(uint32_t* r, uint32_t a) {
    asm volatile("ldmatrix.sync.aligned.m8n8.x4.trans.shared.b16 {%0,%1,%2,%3}, [%4];"
                 : "=r"(r[0]), "=r"(r[1]), "=r"(r[2]), "=r"(r[3]) : "r"(a));
}
__device__ __forceinline__ void mmaf32(float* c, const uint32_t* a, const uint32_t* b) {
    asm volatile("mma.sync.aligned.m16n8k16.row.col.f32.f16.f16.f32 "
                 "{%0,%1,%2,%3}, {%4,%5,%6,%7}, {%8,%9}, {%0,%1,%2,%3};"
                 : "+f"(c[0]), "+f"(c[1]), "+f"(c[2]), "+f"(c[3])
                 : "r"(a[0]), "r"(a[1]), "r"(a[2]), "r"(a[3]), "r"(b[0]), "r"(b[1]));
}
__device__ __forceinline__ void cpa16(uint32_t d, const void* s) {
    asm volatile("cp.async.cg.shared.global [%0], [%1], 16;" :: "r"(d), "l"(s));
}
#define CP_COMMIT() asm volatile("cp.async.commit_group;")
#define CP_WAIT(n)  asm volatile("cp.async.wait_group %0;" :: "n"(n))

__device__ __forceinline__ uint32_t h2pack(float a, float b) {
    __half2 t = __floats2half2_rn(a, b);
    return *reinterpret_cast<uint32_t*>(&t);
}
__device__ __forceinline__ float hres(float a) {
    __half h = __float2half_rn(a);
    return a - __half2float(h);
}

// ================= LayerNorm -> fp16 hi/lo =================
__global__ __launch_bounds__(256) void ln_kernel(const float* __restrict__ x,
                                                 const float* __restrict__ w,
                                                 const float* __restrict__ b) {
    __shared__ float sb1[8], sb2[8];
    int row = blockIdx.x, t = threadIdx.x;
    const float* xr = x + (size_t)row * DIM;
    float v0 = xr[t], v1 = xr[t + 256];
    float s = v0 + v1, ss = v0 * v0 + v1 * v1;
    #pragma unroll
    for (int o = 16; o > 0; o >>= 1) {
        s  += __shfl_xor_sync(~0u, s, o);
        ss += __shfl_xor_sync(~0u, ss, o);
    }
    int lane = t & 31, wd = t >> 5;
    if (lane == 0) { sb1[wd] = s; sb2[wd] = ss; }
    __syncthreads();
    if (wd == 0) {
        float r1 = (lane < 8) ? sb1[lane] : 0.f, r2 = (lane < 8) ? sb2[lane] : 0.f;
        #pragma unroll
        for (int o = 4; o > 0; o >>= 1) {
            r1 += __shfl_xor_sync(~0u, r1, o);
            r2 += __shfl_xor_sync(~0u, r2, o);
        }
        if (lane == 0) { sb1[0] = r1; sb2[0] = r2; }
    }
    __syncthreads();
    float mu  = sb1[0] * (1.f / DIM);
    float var = sb2[0] * (1.f / DIM) - mu * mu;
    float inv = rsqrtf(var + 1e-5f);
    float o0 = (v0 - mu) * inv * w[t] + b[t];
    float o1 = (v1 - mu) * inv * w[t + 256] + b[t + 256];
    size_t base = (size_t)row * DIM;
    g_xnh[base + t] = __float2half_rn(o0);
    g_xnh[base + t + 256] = __float2half_rn(o1);
    g_xnl[base + t] = __float2half_rn(hres(o0));
    g_xnl[base + t + 256] = __float2half_rn(hres(o1));
}

// ================= weight-norm -> fp16 hi/lo =================
__global__ __launch_bounds__(256) void wnorm_kernel(const float* __restrict__ wv_v,
                                                    const float* __restrict__ wv_g) {
    __shared__ float sbuf[8];
    int row = blockIdx.x, t = threadIdx.x;
    const float* vr = wv_v + (size_t)row * DIM;
    float v0 = vr[t], v1 = vr[t + 256];
    float ss = v0 * v0 + v1 * v1;
    #pragma unroll
    for (int o = 16; o > 0; o >>= 1) ss += __shfl_xor_sync(~0u, ss, o);
    int lane = t & 31, wd = t >> 5;
    if (lane == 0) sbuf[wd] = ss;
    __syncthreads();
    if (wd == 0) {
        float r = (lane < 8) ? sbuf[lane] : 0.f;
        #pragma unroll
        for (int o = 4; o > 0; o >>= 1) r += __shfl_xor_sync(~0u, r, o);
        if (lane == 0) sbuf[0] = r;
    }
    __syncthreads();
    float sc = wv_g[row] * rsqrtf(sbuf[0]);
    float o0 = v0 * sc, o1 = v1 * sc;
    size_t base = (size_t)row * DIM;
    g_wvh[base + t] = __float2half_rn(o0);
    g_wvh[base + t + 256] = __float2half_rn(o1);
    g_wvl[base + t] = __float2half_rn(hres(o0));
    g_wvl[base + t + 256] = __float2half_rn(hres(o1));
}

// ================= fused fp32 -> fp16 hi/lo for wq, wk, w_out =================
__global__ __launch_bounds__(256) void conv3_kernel(const float* __restrict__ s0,
                                                    const float* __restrict__ s1,
                                                    const float* __restrict__ s2) {
    int i = blockIdx.x * 256 + threadIdx.x;
    if (i < DIM * DIM) {
        float f0 = s0[i], f1 = s1[i], f2 = s2[i];
        g_wqh[i] = __float2half_rn(f0); g_wql[i] = __float2half_rn(hres(f0));
        g_wkh[i] = __float2half_rn(f1); g_wkl[i] = __float2half_rn(hres(f1));
        g_woh[i] = __float2half_rn(f2); g_wol[i] = __float2half_rn(hres(f2));
    }
}

#define GP 144
#define TT (128 * GP)          // 18432 per tile

// ================= 2-term GEMM (A_hi only): C_hi = A_hi * (B_hi + B_lo)^T =================
// stage = Ah, Bh, Bl (3 tiles). Fused over gridDim.z (two weight/output sets).
#define ST2 (3 * TT)           // 55296 per stage
#define G2_SMEM (2 * ST2)      // 110592

__global__ __launch_bounds__(256, 1)
void gemm2(const __half* __restrict__ Ah,
           const __half* __restrict__ Bh0, const __half* __restrict__ Bl0,
           __half* __restrict__ Ch0, float scale0,
           const __half* __restrict__ Bh1, const __half* __restrict__ Bl1,
           __half* __restrict__ Ch1, float scale1) {
    const __half* Bh = blockIdx.z ? Bh1 : Bh0;
    const __half* Bl = blockIdx.z ? Bl1 : Bl0;
    __half* Ch = blockIdx.z ? Ch1 : Ch0;
    float scale = blockIdx.z ? scale1 : scale0;

    extern __shared__ char sm[];
    uint32_t sb = smem_u32(sm);
    int tid = threadIdx.x, lane = tid & 31, wd = tid >> 5;
    int wm = wd & 3, wn = wd >> 2;
    int tm = blockIdx.y * 128, tn = blockIdx.x * 128;

    float c[2][8][4];
    #pragma unroll
    for (int i = 0; i < 2; i++)
        #pragma unroll
        for (int j = 0; j < 8; j++)
            #pragma unroll
            for (int e = 0; e < 4; e++) c[i][j][e] = 0.f;

    auto stage = [&](int kc, uint32_t buf) {
        int k0 = kc * 64;
        #pragma unroll
        for (int u = 0; u < 4; u++) {
            int e = tid + u * 256;
            int r = e >> 3, c8 = (e & 7) * 8;
            uint32_t d = buf + (uint32_t)r * GP + c8 * 2;
            size_t ga = (size_t)(tm + r) * DIM + k0 + c8;
            size_t gb = (size_t)(tn + r) * DIM + k0 + c8;
            cpa16(d, &Ah[ga]);
            cpa16(d + TT, &Bh[gb]);
            cpa16(d + 2 * TT, &Bl[gb]);
        }
    };

    stage(0, sb);
    CP_COMMIT();

    for (int kc = 0; kc < 8; kc++) {
        CP_WAIT(0);
        __syncthreads();
        if (kc < 7) {
            stage(kc + 1, sb + ((kc + 1) & 1) * ST2);
            CP_COMMIT();
        }
        uint32_t buf = sb + (kc & 1) * ST2;
        #pragma unroll
        for (int ks = 0; ks < 4; ks++) {
            uint32_t ah[2][4];
            uint32_t acol = ks * 32 + ((lane >> 4) << 4);
            #pragma unroll
            for (int mt = 0; mt < 2; mt++) {
                uint32_t arow = wm * 32 + mt * 16 + (lane & 15);
                ldsm4(ah[mt], buf + arow * GP + acol);
            }
            uint32_t bro = ((lane >> 4) << 3) + (lane & 7);
            uint32_t bcol = ks * 32 + (((lane >> 3) & 1) << 4);
            #pragma unroll
            for (int p = 0; p < 4; p++) {
                uint32_t nrow = wn * 64 + p * 16 + bro;
                uint32_t bh[4], bl[4];
                ldsm4(bh, buf + TT + nrow * GP + bcol);
                ldsm4(bl, buf + 2 * TT + nrow * GP + bcol);
                #pragma unroll
                for (int mt = 0; mt < 2; mt++) {
                    mmaf32(c[mt][2 * p],     ah[mt], &bh[0]);
                    mmaf32(c[mt][2 * p],     ah[mt], &bl[0]);
                    mmaf32(c[mt][2 * p + 1], ah[mt], &bh[2]);
                    mmaf32(c[mt][2 * p + 1], ah[mt], &bl[2]);
                }
            }
        }
        __syncthreads();
    }

    int g = lane >> 2, t4 = lane & 3;
    #pragma unroll
    for (int mt = 0; mt < 2; mt++) {
        #pragma unroll
        for (int nt = 0; nt < 8; nt++) {
            int row = tm + wm * 32 + mt * 16 + g;
            int col = tn + wn * 64 + nt * 8 + t4 * 2;
            *(uint32_t*)&Ch[(size_t)row * DIM + col] =
                h2pack(c[mt][nt][0] * scale, c[mt][nt][1] * scale);
            *(uint32_t*)&Ch[(size_t)(row + 8) * DIM + col] =
                h2pack(c[mt][nt][2] * scale, c[mt][nt][3] * scale);
        }
    }
}

// ================= 3-term GEMM (output projection, fp32 out) =================
#define ST3 (4 * TT)           // 73728 per stage
#define G3_SMEM (2 * ST3)      // 147456

__global__ __launch_bounds__(256, 1)
void gemm3(const __half* __restrict__ Ah, const __half* __restrict__ Al,
           const __half* __restrict__ Bh, const __half* __restrict__ Bl,
           float* __restrict__ Cf, float scale) {
    extern __shared__ char sm[];
    uint32_t sb = smem_u32(sm);
    int tid = threadIdx.x, lane = tid & 31, wd = tid >> 5;
    int wm = wd & 3, wn = wd >> 2;
    int tm = blockIdx.y * 128, tn = blockIdx.x * 128;

    float c[2][8][4];
    #pragma unroll
    for (int i = 0; i < 2; i++)
        #pragma unroll
        for (int j = 0; j < 8; j++)
            #pragma unroll
            for (int e = 0; e < 4; e++) c[i][j][e] = 0.f;

    auto stage = [&](int kc, uint32_t buf) {
        int k0 = kc * 64;
        #pragma unroll
        for (int u = 0; u < 4; u++) {
            int e = tid + u * 256;
            int r = e >> 3, c8 = (e & 7) * 8;
            uint32_t d = buf + (uint32_t)r * GP + c8 * 2;
            size_t ga = (size_t)(tm + r) * DIM + k0 + c8;
            size_t gb = (size_t)(tn + r) * DIM + k0 + c8;
            cpa16(d, &Ah[ga]);           cpa16(d + TT, &Al[ga]);
            cpa16(d + 2 * TT, &Bh[gb]);  cpa16(d + 3 * TT, &Bl[gb]);
        }
    };

    stage(0, sb);
    CP_COMMIT();

    for (int kc = 0; kc < 8; kc++) {
        CP_WAIT(0);
        __syncthreads();
        if (kc < 7) {
            stage(kc + 1, sb + ((kc + 1) & 1) * ST3);
            CP_COMMIT();
        }
        uint32_t buf = sb + (kc & 1) * ST3;
        #pragma unroll
        for (int ks = 0; ks < 4; ks++) {
            uint32_t ah[2][4], al[2][4];
            uint32_t acol = ks * 32 + ((lane >> 4) << 4);
            #pragma unroll
            for (int mt = 0; mt < 2; mt++) {
                uint32_t arow = wm * 32 + mt * 16 + (lane & 15);
                ldsm4(ah[mt], buf + arow * GP + acol);
                ldsm4(al[mt], buf + TT + arow * GP + acol);
            }
            uint32_t bro = ((lane >> 4) << 3) + (lane & 7);
            uint32_t bcol = ks * 32 + (((lane >> 3) & 1) << 4);
            #pragma unroll
            for (int p = 0; p < 4; p++) {
                uint32_t nrow = wn * 64 + p * 16 + bro;
                uint32_t bh[4], bl[4];
                ldsm4(bh, buf + 2 * TT + nrow * GP + bcol);
                ldsm4(bl, buf + 3 * TT + nrow * GP + bcol);
                #pragma unroll
                for (int mt = 0; mt < 2; mt++) {
                    mmaf32(c[mt][2 * p],     ah[mt], &bh[0]);
                    mmaf32(c[mt][2 * p],     ah[mt], &bl[0]);
                    mmaf32(c[mt][2 * p],     al[mt], &bh[0]);
                    mmaf32(c[mt][2 * p + 1], ah[mt], &bh[2]);
                    mmaf32(c[mt][2 * p + 1], ah[mt], &bl[2]);
                    mmaf32(c[mt][2 * p + 1], al[mt], &bh[2]);
                }
            }
        }
        __syncthreads();
    }

    int g = lane >> 2, t4 = lane & 3;
    #pragma unroll
    for (int mt = 0; mt < 2; mt++) {
        #pragma unroll
        for (int nt = 0; nt < 8; nt++) {
            int row = tm + wm * 32 + mt * 16 + g;
            int col = tn + wn * 64 + nt * 8 + t4 * 2;
            *(float2*)&Cf[(size_t)row * DIM + col] =
                make_float2(c[mt][nt][0] * scale, c[mt][nt][1] * scale);
            *(float2*)&Cf[(size_t)(row + 8) * DIM + col] =
                make_float2(c[mt][nt][2] * scale, c[mt][nt][3] * scale);
        }
    }
}

// ================= flash attention: 1-term fp16, exp2, occ 2 =================
// Q pre-scaled by log2(e)/8 in projection, so P = exp2(s).
#define AST (64 * GP)           // 9216 per tile
#define A_SMEM (2 * 2 * AST)    // 36864

__global__ __launch_bounds__(256, 2)
void attn_mma(const __half* __restrict__ Qh,
              const __half* __restrict__ Kh,
              const __half* __restrict__ Vh,
              __half* __restrict__ Oh, __half* __restrict__ Ol) {
    extern __shared__ char sm[];
    uint32_t sb = smem_u32(sm);
    int tid = threadIdx.x, lane = tid & 31, wd = tid >> 5;
    int b = blockIdx.x >> 3, h = blockIdx.x & 7;
    int iBase = blockIdx.y * 128;
    size_t base = (size_t)b * NSEQ * DIM + (size_t)h * DHEAD;

    #pragma unroll
    for (int u = 0; u < 4; u++) {
        int e = tid + u * 256;
        int r = e >> 3, c8 = (e & 7) * 8;
        uint32_t d = sb + (uint32_t)r * GP + c8 * 2;
        size_t ga = base + (size_t)(iBase + r) * DIM + c8;
        cpa16(d, &Qh[ga]);
    }
    CP_COMMIT(); CP_WAIT(0);
    __syncthreads();

    uint32_t qh[4][4];
    {
        uint32_t arow = wd * 16 + (lane & 15);
        #pragma unroll
        for (int ks = 0; ks < 4; ks++) {
            uint32_t acol = ks * 32 + ((lane >> 4) << 4);
            ldsm4(qh[ks], sb + arow * GP + acol);
        }
    }
    __syncthreads();

    float o[8][4];
    #pragma unroll
    for (int i = 0; i < 8; i++)
        #pragma unroll
        for (int e = 0; e < 4; e++) o[i][e] = 0.f;
    float l0 = 0.f, l1 = 0.f;

    auto stage_kv = [&](int blk, uint32_t buf) {
        int j0 = blk * 64;
        #pragma unroll
        for (int u = 0; u < 2; u++) {
            int e = tid + u * 256;
            int r = e >> 3, c8 = (e & 7) * 8;
            uint32_t d = buf + (uint32_t)r * GP + c8 * 2;
            size_t ga = base + (size_t)(j0 + r) * DIM + c8;
            cpa16(d, &Kh[ga]);
            cpa16(d + AST, &Vh[ga]);
        }
    };

    stage_kv(0, sb);
    CP_COMMIT();

    for (int bi = 0; bi < 32; bi++) {
        CP_WAIT(0);
        __syncthreads();
        uint32_t buf = sb + (bi & 1) * 2 * AST;
        if (bi < 31) {
            stage_kv(bi + 1, sb + ((bi + 1) & 1) * 2 * AST);
            CP_COMMIT();
        }

        float s[8][4];
        #pragma unroll
        for (int nt = 0; nt < 8; nt++)
            #pragma unroll
            for (int e = 0; e < 4; e++) s[nt][e] = 0.f;

        uint32_t bro = ((lane >> 4) << 3) + (lane & 7);
        #pragma unroll
        for (int ks = 0; ks < 4; ks++) {
            uint32_t bcol = ks * 32 + (((lane >> 3) & 1) << 4);
            #pragma unroll
            for (int p = 0; p < 4; p++) {
                uint32_t nrow = p * 16 + bro;
                uint32_t bh[4];
                ldsm4(bh, buf + nrow * GP + bcol);
                mmaf32(s[2 * p],     qh[ks], &bh[0]);
                mmaf32(s[2 * p + 1], qh[ks], &bh[2]);
            }
        }

        // P = exp2(s) == exp(raw score): log2e folded into Q scale
        #pragma unroll
        for (int nt = 0; nt < 8; nt++) {
            s[nt][0] = exp2f(s[nt][0]);
            s[nt][1] = exp2f(s[nt][1]);
            s[nt][2] = exp2f(s[nt][2]);
            s[nt][3] = exp2f(s[nt][3]);
            l0 += s[nt][0] + s[nt][1];
            l1 += s[nt][2] + s[nt][3];
        }

        uint32_t vro = (((lane >> 3) & 1) << 3) + (lane & 7);
        uint32_t vco = (lane >> 4) << 4;
        #pragma unroll
        for (int st = 0; st < 4; st++) {
            uint32_t a_h[4];
            a_h[0] = h2pack(s[2 * st][0], s[2 * st][1]);
            a_h[1] = h2pack(s[2 * st][2], s[2 * st][3]);
            a_h[2] = h2pack(s[2 * st + 1][0], s[2 * st + 1][1]);
            a_h[3] = h2pack(s[2 * st + 1][2], s[2 * st + 1][3]);
            uint32_t jrow = st * 16 + vro;
            #pragma unroll
            for (int dp = 0; dp < 4; dp++) {
                uint32_t db = dp * 32 + vco;
                uint32_t vh[4];
                ldsm4t(vh, buf + AST + jrow * GP + db);
                mmaf32(o[2 * dp],     a_h, &vh[0]);
                mmaf32(o[2 * dp + 1], a_h, &vh[2]);
            }
        }
        __syncthreads();
    }

    l0 += __shfl_xor_sync(~0u, l0, 1); l0 += __shfl_xor_sync(~0u, l0, 2);
    l1 += __shfl_xor_sync(~0u, l1, 1); l1 += __shfl_xor_sync(~0u, l1, 2);
    // store att * 16 so the lo residual stays fp16-normal; undone in output GEMM
    float i0v = 16.f / l0, i1v = 16.f / l1;

    int g = lane >> 2, t4 = lane & 3;
    size_t ga0 = base + (size_t)(iBase + wd * 16 + g) * DIM + t4 * 2;
    size_t ga1 = ga0 + 8 * DIM;
    #pragma unroll
    for (int dt = 0; dt < 8; dt++) {
        float x0 = o[dt][0] * i0v, x1 = o[dt][1] * i0v;
        float y0 = o[dt][2] * i1v, y1 = o[dt][3] * i1v;
        *(uint32_t*)&Oh[ga0 + dt * 8] = h2pack(x0, x1);
        *(uint32_t*)&Ol[ga0 + dt * 8] = h2pack(hres(x0), hres(x1));
        *(uint32_t*)&Oh[ga1 + dt * 8] = h2pack(y0, y1);
        *(uint32_t*)&Ol[ga1 + dt * 8] = h2pack(hres(y0), hres(y1));
    }
}

// ================= launch =================
extern "C" void kernel_launch(void* const* d_in, const int* in_sizes, int n_in,
                              void* d_out, int out_size) {
    const float* x     = (const float*)d_in[0];
    const float* ln_w  = (const float*)d_in[1];
    const float* ln_b  = (const float*)d_in[2];
    const float* wq    = (const float*)d_in[3];
    const float* wk    = (const float*)d_in[4];
    const float* wv_v  = (const float*)d_in[5];
    const float* wv_g  = (const float*)d_in[6];
    const float* w_out = (const float*)d_in[7];
    float* out = (float*)d_out;

    __half *xnh, *xnl, *ath, *atl, *qh, *kh, *vh;
    __half *wqh, *wql, *wkh, *wkl, *wvh, *wvl, *woh, *wol;
    cudaGetSymbolAddress((void**)&xnh, g_xnh); cudaGetSymbolAddress((void**)&xnl, g_xnl);
    cudaGetSymbolAddress((void**)&ath, g_ath); cudaGetSymbolAddress((void**)&atl, g_atl);
    cudaGetSymbolAddress((void**)&qh, g_qh);
    cudaGetSymbolAddress((void**)&kh, g_kh);
    cudaGetSymbolAddress((void**)&vh, g_vh);
    cudaGetSymbolAddress((void**)&wqh, g_wqh); cudaGetSymbolAddress((void**)&wql, g_wql);
    cudaGetSymbolAddress((void**)&wkh, g_wkh); cudaGetSymbolAddress((void**)&wkl, g_wkl);
    cudaGetSymbolAddress((void**)&wvh, g_wvh); cudaGetSymbolAddress((void**)&wvl, g_wvl);
    cudaGetSymbolAddress((void**)&woh, g_woh); cudaGetSymbolAddress((void**)&wol, g_wol);

    cudaFuncSetAttribute(gemm2, cudaFuncAttributeMaxDynamicSharedMemorySize, G2_SMEM);
    cudaFuncSetAttribute(gemm3, cudaFuncAttributeMaxDynamicSharedMemorySize, G3_SMEM);
    cudaFuncSetAttribute(attn_mma, cudaFuncAttributeMaxDynamicSharedMemorySize, A_SMEM);

    const float QSCALE = 0.125f * 1.44269504088896f;  // (1/8) * log2(e)

    // launch order: attn is the 6th launch -> ncu -s 5 -c 1 captures it
    ln_kernel<<<ROWS, 256>>>(x, ln_w, ln_b);                                   // 1
    conv3_kernel<<<(DIM * DIM + 255) / 256, 256>>>(wq, wk, w_out);             // 2
    wnorm_kernel<<<DIM, 256>>>(wv_v, wv_g);                                    // 3

    dim3 gq(DIM / 128, ROWS / 128, 1);
    dim3 gkv(DIM / 128, ROWS / 128, 2);
    gemm2<<<gq, 256, G2_SMEM>>>(xnh, wqh, wql, qh, QSCALE,
                                wqh, wql, qh, QSCALE);                         // 4
    gemm2<<<gkv, 256, G2_SMEM>>>(xnh, wkh, wkl, kh, 1.0f,
                                 wvh, wvl, vh, 1.0f);                          // 5
    attn_mma<<<dim3(32, 16), 256, A_SMEM>>>(qh, kh, vh, ath, atl);             // 6
    gemm3<<<gq, 256, G3_SMEM>>>(ath, atl, woh, wol, out, 1.0f / 16.0f);        // 7
}

// round 14
// speedup vs baseline: 2.5238x; 1.3157x over previous
#include <cuda_runtime.h>
#include <cuda_fp16.h>
#include <cstdint>

#define DIM 512
#define HEADS 8
#define DHEAD 64
#define BATCH 4
#define NSEQ 2048
#define ROWS (BATCH * NSEQ)   // 8192

// ================= scratch (no allocations allowed) =================
__device__ __half g_xnh[ROWS * DIM];
__device__ __half g_qh[ROWS * DIM];
__device__ __half g_kh[ROWS * DIM];
__device__ __half g_vh[ROWS * DIM];
__device__ __half g_ath[ROWS * DIM];
__device__ __half g_wqh[DIM * DIM];
__device__ __half g_wkh[DIM * DIM];
__device__ __half g_wvh[DIM * DIM];
__device__ __half g_woh[DIM * DIM], g_wol[DIM * DIM];

// ================= helpers =================
__device__ __forceinline__ uint32_t smem_u32(const void* p) {
    uint32_t a;
    asm("{ .reg .u64 t; cvta.to.shared.u64 t, %1; cvt.u32.u64 %0, t; }" : "=r"(a) : "l"(p));
    return a;
}
__device__ __forceinline__ void ldsm4(uint32_t* r, uint32_t a) {
    asm volatile("ldmatrix.sync.aligned.m8n8.x4.shared.b16 {%0,%1,%2,%3}, [%4];"
                 : "=r"(r[0]), "=r"(r[1]), "=r"(r[2]), "=r"(r[3]) : "r"(a));
}
__device__ __forceinline__ void ldsm4t(uint32_t* r, uint32_t a) {
    asm volatile("ldmatrix.sync.aligned.m8n8.x4.trans.shared.b16 {%0,%1,%2,%3}, [%4];"
                 : "=r"(r[0]), "=r"(r[1]), "=r"(r[2]), "=r"(r[3]) : "r"(a));
}
__device__ __forceinline__ void mmaf32(float* c, const uint32_t* a, const uint32_t* b) {
    asm volatile("mma.sync.aligned.m16n8k16.row.col.f32.f16.f16.f32 "
                 "{%0,%1,%2,%3}, {%4,%5,%6,%7}, {%8,%9}, {%0,%1,%2,%3};"
                 : "+f"(c[0]), "+f"(c[1]), "+f"(c[2]), "+f"(c[3])
                 : "r"(a[0]), "r"(a[1]), "r"(a[2]), "r"(a[3]), "r"(b[0]), "r"(b[1]));
}
__device__ __forceinline__ void cpa16(uint32_t d, const void* s) {
    asm volatile("cp.async.cg.shared.global [%0], [%1], 16;" :: "r"(d), "l"(s));
}
#define CP_COMMIT() asm volatile("cp.async.commit_group;")
#define CP_WAIT(n)  asm volatile("cp.async.wait_group %0;" :: "n"(n))

__device__ __forceinline__ uint32_t h2pack(float a, float b) {
    __half2 t = __floats2half2_rn(a, b);
    return *reinterpret_cast<uint32_t*>(&t);
}
__device__ __forceinline__ float hres(float a) {
    __half h = __float2half_rn(a);
    return a - __half2float(h);
}

// ================= LayerNorm -> fp16 =================
__global__ __launch_bounds__(256) void ln_kernel(const float* __restrict__ x,
                                                 const float* __restrict__ w,
                                                 const float* __restrict__ b) {
    __shared__ float sb1[8], sb2[8];
    int row = blockIdx.x, t = threadIdx.x;
    const float* xr = x + (size_t)row * DIM;
    float v0 = xr[t], v1 = xr[t + 256];
    float s = v0 + v1, ss = v0 * v0 + v1 * v1;
    #pragma unroll
    for (int o = 16; o > 0; o >>= 1) {
        s  += __shfl_xor_sync(~0u, s, o);
        ss += __shfl_xor_sync(~0u, ss, o);
    }
    int lane = t & 31, wd = t >> 5;
    if (lane == 0) { sb1[wd] = s; sb2[wd] = ss; }
    __syncthreads();
    if (wd == 0) {
        float r1 = (lane < 8) ? sb1[lane] : 0.f, r2 = (lane < 8) ? sb2[lane] : 0.f;
        #pragma unroll
        for (int o = 4; o > 0; o >>= 1) {
            r1 += __shfl_xor_sync(~0u, r1, o);
            r2 += __shfl_xor_sync(~0u, r2, o);
        }
        if (lane == 0) { sb1[0] = r1; sb2[0] = r2; }
    }
    __syncthreads();
    float mu  = sb1[0] * (1.f / DIM);
    float var = sb2[0] * (1.f / DIM) - mu * mu;
    float inv = rsqrtf(var + 1e-5f);
    size_t base = (size_t)row * DIM;
    g_xnh[base + t]       = __float2half_rn((v0 - mu) * inv * w[t] + b[t]);
    g_xnh[base + t + 256] = __float2half_rn((v1 - mu) * inv * w[t + 256] + b[t + 256]);
}

// ================= weight-norm -> fp16 =================
__global__ __launch_bounds__(256) void wnorm_kernel(const float* __restrict__ wv_v,
                                                    const float* __restrict__ wv_g) {
    __shared__ float sbuf[8];
    int row = blockIdx.x, t = threadIdx.x;
    const float* vr = wv_v + (size_t)row * DIM;
    float v0 = vr[t], v1 = vr[t + 256];
    float ss = v0 * v0 + v1 * v1;
    #pragma unroll
    for (int o = 16; o > 0; o >>= 1) ss += __shfl_xor_sync(~0u, ss, o);
    int lane = t & 31, wd = t >> 5;
    if (lane == 0) sbuf[wd] = ss;
    __syncthreads();
    if (wd == 0) {
        float r = (lane < 8) ? sbuf[lane] : 0.f;
        #pragma unroll
        for (int o = 4; o > 0; o >>= 1) r += __shfl_xor_sync(~0u, r, o);
        if (lane == 0) sbuf[0] = r;
    }
    __syncthreads();
    float sc = wv_g[row] * rsqrtf(sbuf[0]);
    size_t base = (size_t)row * DIM;
    g_wvh[base + t]       = __float2half_rn(v0 * sc);
    g_wvh[base + t + 256] = __float2half_rn(v1 * sc);
}

// ================= fused weight conversion =================
__global__ __launch_bounds__(256) void conv3_kernel(const float* __restrict__ s0,
                                                    const float* __restrict__ s1,
                                                    const float* __restrict__ s2) {
    int i = blockIdx.x * 256 + threadIdx.x;
    if (i < DIM * DIM) {
        g_wqh[i] = __float2half_rn(s0[i]);
        g_wkh[i] = __float2half_rn(s1[i]);
        float f2 = s2[i];
        g_woh[i] = __float2half_rn(f2);
        g_wol[i] = __float2half_rn(hres(f2));
    }
}

#define GP 144
#define TT (128 * GP)          // 18432 per tile

// ================= 1-term fp16 GEMM (QKV, fused over z) =================
#define ST1 (2 * TT)           // 36864 per stage
#define G1_SMEM (2 * ST1)      // 73728

__global__ __launch_bounds__(256, 2)
void gemm1(const __half* __restrict__ Ah,
           const __half* __restrict__ B0, __half* __restrict__ C0, float s0,
           const __half* __restrict__ B1, __half* __restrict__ C1, float s1,
           const __half* __restrict__ B2, __half* __restrict__ C2, float s2) {
    const __half* Bh = blockIdx.z == 0 ? B0 : (blockIdx.z == 1 ? B1 : B2);
    __half* Ch = blockIdx.z == 0 ? C0 : (blockIdx.z == 1 ? C1 : C2);
    float scale = blockIdx.z == 0 ? s0 : (blockIdx.z == 1 ? s1 : s2);

    extern __shared__ char sm[];
    uint32_t sb = smem_u32(sm);
    int tid = threadIdx.x, lane = tid & 31, wd = tid >> 5;
    int wm = wd & 3, wn = wd >> 2;
    int tm = blockIdx.y * 128, tn = blockIdx.x * 128;

    float c[2][8][4];
    #pragma unroll
    for (int i = 0; i < 2; i++)
        #pragma unroll
        for (int j = 0; j < 8; j++)
            #pragma unroll
            for (int e = 0; e < 4; e++) c[i][j][e] = 0.f;

    auto stage = [&](int kc, uint32_t buf) {
        int k0 = kc * 64;
        #pragma unroll
        for (int u = 0; u < 4; u++) {
            int e = tid + u * 256;
            int r = e >> 3, c8 = (e & 7) * 8;
            uint32_t d = buf + (uint32_t)r * GP + c8 * 2;
            cpa16(d, &Ah[(size_t)(tm + r) * DIM + k0 + c8]);
            cpa16(d + TT, &Bh[(size_t)(tn + r) * DIM + k0 + c8]);
        }
    };

    stage(0, sb);
    CP_COMMIT();

    for (int kc = 0; kc < 8; kc++) {
        CP_WAIT(0);
        __syncthreads();
        if (kc < 7) {
            stage(kc + 1, sb + ((kc + 1) & 1) * ST1);
            CP_COMMIT();
        }
        uint32_t buf = sb + (kc & 1) * ST1;
        #pragma unroll
        for (int ks = 0; ks < 4; ks++) {
            uint32_t ah[2][4];
            uint32_t acol = ks * 32 + ((lane >> 4) << 4);
            #pragma unroll
            for (int mt = 0; mt < 2; mt++) {
                uint32_t arow = wm * 32 + mt * 16 + (lane & 15);
                ldsm4(ah[mt], buf + arow * GP + acol);
            }
            uint32_t bro = ((lane >> 4) << 3) + (lane & 7);
            uint32_t bcol = ks * 32 + (((lane >> 3) & 1) << 4);
            #pragma unroll
            for (int p = 0; p < 4; p++) {
                uint32_t nrow = wn * 64 + p * 16 + bro;
                uint32_t bh[4];
                ldsm4(bh, buf + TT + nrow * GP + bcol);
                #pragma unroll
                for (int mt = 0; mt < 2; mt++) {
                    mmaf32(c[mt][2 * p],     ah[mt], &bh[0]);
                    mmaf32(c[mt][2 * p + 1], ah[mt], &bh[2]);
                }
            }
        }
        __syncthreads();
    }

    int g = lane >> 2, t4 = lane & 3;
    #pragma unroll
    for (int mt = 0; mt < 2; mt++) {
        #pragma unroll
        for (int nt = 0; nt < 8; nt++) {
            int row = tm + wm * 32 + mt * 16 + g;
            int col = tn + wn * 64 + nt * 8 + t4 * 2;
            *(uint32_t*)&Ch[(size_t)row * DIM + col] =
                h2pack(c[mt][nt][0] * scale, c[mt][nt][1] * scale);
            *(uint32_t*)&Ch[(size_t)(row + 8) * DIM + col] =
                h2pack(c[mt][nt][2] * scale, c[mt][nt][3] * scale);
        }
    }
}

// ================= 2-term output GEMM: C_f = A_h * (B_h + B_l)^T =================
#define STO (3 * TT)           // 55296 per stage
#define GO_SMEM (2 * STO)      // 110592

__global__ __launch_bounds__(256, 1)
void gemmO(const __half* __restrict__ Ah,
           const __half* __restrict__ Bh, const __half* __restrict__ Bl,
           float* __restrict__ Cf) {
    extern __shared__ char sm[];
    uint32_t sb = smem_u32(sm);
    int tid = threadIdx.x, lane = tid & 31, wd = tid >> 5;
    int wm = wd & 3, wn = wd >> 2;
    int tm = blockIdx.y * 128, tn = blockIdx.x * 128;

    float c[2][8][4];
    #pragma unroll
    for (int i = 0; i < 2; i++)
        #pragma unroll
        for (int j = 0; j < 8; j++)
            #pragma unroll
            for (int e = 0; e < 4; e++) c[i][j][e] = 0.f;

    auto stage = [&](int kc, uint32_t buf) {
        int k0 = kc * 64;
        #pragma unroll
        for (int u = 0; u < 4; u++) {
            int e = tid + u * 256;
            int r = e >> 3, c8 = (e & 7) * 8;
            uint32_t d = buf + (uint32_t)r * GP + c8 * 2;
            cpa16(d, &Ah[(size_t)(tm + r) * DIM + k0 + c8]);
            cpa16(d + TT, &Bh[(size_t)(tn + r) * DIM + k0 + c8]);
            cpa16(d + 2 * TT, &Bl[(size_t)(tn + r) * DIM + k0 + c8]);
        }
    };

    stage(0, sb);
    CP_COMMIT();

    for (int kc = 0; kc < 8; kc++) {
        CP_WAIT(0);
        __syncthreads();
        if (kc < 7) {
            stage(kc + 1, sb + ((kc + 1) & 1) * STO);
            CP_COMMIT();
        }
        uint32_t buf = sb + (kc & 1) * STO;
        #pragma unroll
        for (int ks = 0; ks < 4; ks++) {
            uint32_t ah[2][4];
            uint32_t acol = ks * 32 + ((lane >> 4) << 4);
            #pragma unroll
            for (int mt = 0; mt < 2; mt++) {
                uint32_t arow = wm * 32 + mt * 16 + (lane & 15);
                ldsm4(ah[mt], buf + arow * GP + acol);
            }
            uint32_t bro = ((lane >> 4) << 3) + (lane & 7);
            uint32_t bcol = ks * 32 + (((lane >> 3) & 1) << 4);
            #pragma unroll
            for (int p = 0; p < 4; p++) {
                uint32_t nrow = wn * 64 + p * 16 + bro;
                uint32_t bh[4], bl[4];
                ldsm4(bh, buf + TT + nrow * GP + bcol);
                ldsm4(bl, buf + 2 * TT + nrow * GP + bcol);
                #pragma unroll
                for (int mt = 0; mt < 2; mt++) {
                    mmaf32(c[mt][2 * p],     ah[mt], &bh[0]);
                    mmaf32(c[mt][2 * p],     ah[mt], &bl[0]);
                    mmaf32(c[mt][2 * p + 1], ah[mt], &bh[2]);
                    mmaf32(c[mt][2 * p + 1], ah[mt], &bl[2]);
                }
            }
        }
        __syncthreads();
    }

    int g = lane >> 2, t4 = lane & 3;
    #pragma unroll
    for (int mt = 0; mt < 2; mt++) {
        #pragma unroll
        for (int nt = 0; nt < 8; nt++) {
            int row = tm + wm * 32 + mt * 16 + g;
            int col = tn + wn * 64 + nt * 8 + t4 * 2;
            *(float2*)&Cf[(size_t)row * DIM + col] =
                make_float2(c[mt][nt][0], c[mt][nt][1]);
            *(float2*)&Cf[(size_t)(row + 8) * DIM + col] =
                make_float2(c[mt][nt][2], c[mt][nt][3]);
        }
    }
}

// ================= flash attention: 1-term fp16, exp2, occ 2 =================
// Q pre-scaled by log2(e)/8 in projection, so P = exp2(s).
#define AST (64 * GP)           // 9216 per tile
#define A_SMEM (2 * 2 * AST)    // 36864

__global__ __launch_bounds__(256, 2)
void attn_mma(const __half* __restrict__ Qh,
              const __half* __restrict__ Kh,
              const __half* __restrict__ Vh,
              __half* __restrict__ Oh) {
    extern __shared__ char sm[];
    uint32_t sb = smem_u32(sm);
    int tid = threadIdx.x, lane = tid & 31, wd = tid >> 5;
    int b = blockIdx.x >> 3, h = blockIdx.x & 7;
    int iBase = blockIdx.y * 128;
    size_t base = (size_t)b * NSEQ * DIM + (size_t)h * DHEAD;

    #pragma unroll
    for (int u = 0; u < 4; u++) {
        int e = tid + u * 256;
        int r = e >> 3, c8 = (e & 7) * 8;
        uint32_t d = sb + (uint32_t)r * GP + c8 * 2;
        cpa16(d, &Qh[base + (size_t)(iBase + r) * DIM + c8]);
    }
    CP_COMMIT(); CP_WAIT(0);
    __syncthreads();

    uint32_t qh[4][4];
    {
        uint32_t arow = wd * 16 + (lane & 15);
        #pragma unroll
        for (int ks = 0; ks < 4; ks++) {
            uint32_t acol = ks * 32 + ((lane >> 4) << 4);
            ldsm4(qh[ks], sb + arow * GP + acol);
        }
    }
    __syncthreads();

    float o[8][4];
    #pragma unroll
    for (int i = 0; i < 8; i++)
        #pragma unroll
        for (int e = 0; e < 4; e++) o[i][e] = 0.f;
    float l0 = 0.f, l1 = 0.f;

    auto stage_kv = [&](int blk, uint32_t buf) {
        int j0 = blk * 64;
        #pragma unroll
        for (int u = 0; u < 2; u++) {
            int e = tid + u * 256;
            int r = e >> 3, c8 = (e & 7) * 8;
            uint32_t d = buf + (uint32_t)r * GP + c8 * 2;
            size_t ga = base + (size_t)(j0 + r) * DIM + c8;
            cpa16(d, &Kh[ga]);
            cpa16(d + AST, &Vh[ga]);
        }
    };

    stage_kv(0, sb);
    CP_COMMIT();

    for (int bi = 0; bi < 32; bi++) {
        CP_WAIT(0);
        __syncthreads();
        uint32_t buf = sb + (bi & 1) * 2 * AST;
        if (bi < 31) {
            stage_kv(bi + 1, sb + ((bi + 1) & 1) * 2 * AST);
            CP_COMMIT();
        }

        float s[8][4];
        #pragma unroll
        for (int nt = 0; nt < 8; nt++)
            #pragma unroll
            for (int e = 0; e < 4; e++) s[nt][e] = 0.f;

        uint32_t bro = ((lane >> 4) << 3) + (lane & 7);
        #pragma unroll
        for (int ks = 0; ks < 4; ks++) {
            uint32_t bcol = ks * 32 + (((lane >> 3) & 1) << 4);
            #pragma unroll
            for (int p = 0; p < 4; p++) {
                uint32_t nrow = p * 16 + bro;
                uint32_t bh[4];
                ldsm4(bh, buf + nrow * GP + bcol);
                mmaf32(s[2 * p],     qh[ks], &bh[0]);
                mmaf32(s[2 * p + 1], qh[ks], &bh[2]);
            }
        }

        #pragma unroll
        for (int nt = 0; nt < 8; nt++) {
            s[nt][0] = exp2f(s[nt][0]);
            s[nt][1] = exp2f(s[nt][1]);
            s[nt][2] = exp2f(s[nt][2]);
            s[nt][3] = exp2f(s[nt][3]);
            l0 += s[nt][0] + s[nt][1];
            l1 += s[nt][2] + s[nt][3];
        }

        uint32_t vro = (((lane >> 3) & 1) << 3) + (lane & 7);
        uint32_t vco = (lane >> 4) << 4;
        #pragma unroll
        for (int st = 0; st < 4; st++) {
            uint32_t a_h[4];
            a_h[0] = h2pack(s[2 * st][0], s[2 * st][1]);
            a_h[1] = h2pack(s[2 * st][2], s[2 * st][3]);
            a_h[2] = h2pack(s[2 * st + 1][0], s[2 * st + 1][1]);
            a_h[3] = h2pack(s[2 * st + 1][2], s[2 * st + 1][3]);
            uint32_t jrow = st * 16 + vro;
            #pragma unroll
            for (int dp = 0; dp < 4; dp++) {
                uint32_t db = dp * 32 + vco;
                uint32_t vh[4];
                ldsm4t(vh, buf + AST + jrow * GP + db);
                mmaf32(o[2 * dp],     a_h, &vh[0]);
                mmaf32(o[2 * dp + 1], a_h, &vh[2]);
            }
        }
        __syncthreads();
    }

    l0 += __shfl_xor_sync(~0u, l0, 1); l0 += __shfl_xor_sync(~0u, l0, 2);
    l1 += __shfl_xor_sync(~0u, l1, 1); l1 += __shfl_xor_sync(~0u, l1, 2);
    float i0v = 1.f / l0, i1v = 1.f / l1;

    int g = lane >> 2, t4 = lane & 3;
    size_t ga0 = base + (size_t)(iBase + wd * 16 + g) * DIM + t4 * 2;
    size_t ga1 = ga0 + 8 * DIM;
    #pragma unroll
    for (int dt = 0; dt < 8; dt++) {
        *(uint32_t*)&Oh[ga0 + dt * 8] = h2pack(o[dt][0] * i0v, o[dt][1] * i0v);
        *(uint32_t*)&Oh[ga1 + dt * 8] = h2pack(o[dt][2] * i1v, o[dt][3] * i1v);
    }
}

// ================= launch =================
extern "C" void kernel_launch(void* const* d_in, const int* in_sizes, int n_in,
                              void* d_out, int out_size) {
    const float* x     = (const float*)d_in[0];
    const float* ln_w  = (const float*)d_in[1];
    const float* ln_b  = (const float*)d_in[2];
    const float* wq    = (const float*)d_in[3];
    const float* wk    = (const float*)d_in[4];
    const float* wv_v  = (const float*)d_in[5];
    const float* wv_g  = (const float*)d_in[6];
    const float* w_out = (const float*)d_in[7];
    float* out = (float*)d_out;

    __half *xnh, *ath, *qh, *kh, *vh;
    __half *wqh, *wkh, *wvh, *woh, *wol;
    cudaGetSymbolAddress((void**)&xnh, g_xnh);
    cudaGetSymbolAddress((void**)&ath, g_ath);
    cudaGetSymbolAddress((void**)&qh, g_qh);
    cudaGetSymbolAddress((void**)&kh, g_kh);
    cudaGetSymbolAddress((void**)&vh, g_vh);
    cudaGetSymbolAddress((void**)&wqh, g_wqh);
    cudaGetSymbolAddress((void**)&wkh, g_wkh);
    cudaGetSymbolAddress((void**)&wvh, g_wvh);
    cudaGetSymbolAddress((void**)&woh, g_woh);
    cudaGetSymbolAddress((void**)&wol, g_wol);

    cudaFuncSetAttribute(gemm1, cudaFuncAttributeMaxDynamicSharedMemorySize, G1_SMEM);
    cudaFuncSetAttribute(gemmO, cudaFuncAttributeMaxDynamicSharedMemorySize, GO_SMEM);
    cudaFuncSetAttribute(attn_mma, cudaFuncAttributeMaxDynamicSharedMemorySize, A_SMEM);

    const float QSCALE = 0.125f * 1.44269504088896f;  // (1/8) * log2(e)

    ln_kernel<<<ROWS, 256>>>(x, ln_w, ln_b);
    conv3_kernel<<<(DIM * DIM + 255) / 256, 256>>>(wq, wk, w_out);
    wnorm_kernel<<<DIM, 256>>>(wv_v, wv_g);

    dim3 gqkv(DIM / 128, ROWS / 128, 3);
    gemm1<<<gqkv, 256, G1_SMEM>>>(xnh,
                                  wqh, qh, QSCALE,
                                  wkh, kh, 1.0f,
                                  wvh, vh, 1.0f);

    attn_mma<<<dim3(32, 16), 256, A_SMEM>>>(qh, kh, vh, ath);

    gemmO<<<dim3(DIM / 128, ROWS / 128), 256, GO_SMEM>>>(ath, woh, wol, out);
}